// round 11
// baseline (speedup 1.0000x reference)
#include <cuda_runtime.h>
#include <cuda_fp16.h>
#include <cstdint>

#define NNODES 100000
#define FDIM   128
#define NTILES ((NNODES + 127) / 128)

// ---- device-global scratch (allocations forbidden) ----
__device__ __half g_LfPH[(size_t)NNODES * FDIM]; // Lf + feat  fp16 (GEMM A, k 0..127)
__device__ __half g_LiH [(size_t)NNODES * FDIM]; // A @ P      fp16 (GEMM A, k 128..255)
__device__ __half g_featH[(size_t)NNODES * FDIM];// fp16 copy of features
__device__ __half g_PH  [(size_t)NNODES * FDIM]; // Lf * feat fp16 (spmm2 input)
__device__ int    g_rowcnt[NNODES];
__device__ int    g_rowptr[NNODES + 1];
__device__ int    g_rowcur[NNODES];
__device__ int2   g_csr[1600000 + 1024];         // (col, float_bits(val)) packed

#define SCAN_B 1024
#define SCAN_G ((NNODES + SCAN_B - 1) / SCAN_B)  // 98
// decoupled-lookback state: low 32 = value, high 32 = flag (0/1=aggregate/2=prefix)
__device__ unsigned long long g_scanpkt[SCAN_G];

// ---------------------------------------------------------------------------
// Fused kernel: [cvt blocks] feat->fp16 copy | [hist blocks] row histogram
//               | [last block] clear scan flags
// ---------------------------------------------------------------------------
__global__ void fused_cvt_hist_kernel(const float* __restrict__ feat,
                                      const int*   __restrict__ erow,
                                      int nnz, int cvt_blocks, int hist_blocks) {
    int b = blockIdx.x;
    if (b < cvt_blocks) {
        size_t i = (size_t)b * blockDim.x + threadIdx.x;   // per 8 floats
        const size_t total = (size_t)NNODES * FDIM / 8;
        if (i < total) {
            const float4* s = reinterpret_cast<const float4*>(feat) + i * 2;
            float4 a = s[0], bb = s[1];
            __half2 h0 = __floats2half2_rn(a.x, a.y);
            __half2 h1 = __floats2half2_rn(a.z, a.w);
            __half2 h2 = __floats2half2_rn(bb.x, bb.y);
            __half2 h3 = __floats2half2_rn(bb.z, bb.w);
            uint4 st = make_uint4(*reinterpret_cast<uint32_t*>(&h0),
                                  *reinterpret_cast<uint32_t*>(&h1),
                                  *reinterpret_cast<uint32_t*>(&h2),
                                  *reinterpret_cast<uint32_t*>(&h3));
            reinterpret_cast<uint4*>(g_featH)[i] = st;
        }
    } else if (b < cvt_blocks + hist_blocks) {
        int i = ((b - cvt_blocks) * blockDim.x + threadIdx.x) * 4;
        if (i + 3 < nnz) {
            int4 r = *reinterpret_cast<const int4*>(erow + i);
            atomicAdd(&g_rowcnt[r.x], 1);
            atomicAdd(&g_rowcnt[r.y], 1);
            atomicAdd(&g_rowcnt[r.z], 1);
            atomicAdd(&g_rowcnt[r.w], 1);
        } else {
            for (int j = i; j < nnz; j++) atomicAdd(&g_rowcnt[erow[j]], 1);
        }
    } else {
        if (threadIdx.x < SCAN_G) g_scanpkt[threadIdx.x] = 0ull;
    }
}

// ---------------------------------------------------------------------------
// Single-kernel exclusive scan (decoupled lookback, 98 co-resident blocks).
// Writes g_rowptr / g_rowcur.
// ---------------------------------------------------------------------------
__global__ __launch_bounds__(SCAN_B, 1)
void scan_lookback_kernel() {
    __shared__ int s[SCAN_B];
    __shared__ int s_excl;
    const int tid = threadIdx.x;
    const int b   = blockIdx.x;
    const int i   = b * SCAN_B + tid;
    int v = (i < NNODES) ? g_rowcnt[i] : 0;

    // block-local inclusive scan (Hillis-Steele)
    s[tid] = v;
    __syncthreads();
    for (int off = 1; off < SCAN_B; off <<= 1) {
        int t = (tid >= off) ? s[tid - off] : 0;
        __syncthreads();
        s[tid] += t;
        __syncthreads();
    }
    int incl  = s[tid];
    int total = s[SCAN_B - 1];

    if (tid == 0) {
        volatile unsigned long long* pkt = g_scanpkt;
        if (b == 0) {
            pkt[0] = ((unsigned long long)2 << 32) | (unsigned int)total;
            s_excl = 0;
        } else {
            // publish aggregate
            pkt[b] = ((unsigned long long)1 << 32) | (unsigned int)total;
            // lookback
            int excl = 0;
            for (int j = b - 1; j >= 0; ) {
                unsigned long long p;
                do { p = pkt[j]; } while ((p >> 32) == 0ull);
                excl += (int)(unsigned int)p;
                if ((p >> 32) == 2ull) break;
                j--;
            }
            // publish inclusive prefix
            pkt[b] = ((unsigned long long)2 << 32) | (unsigned int)(excl + total);
            s_excl = excl;
        }
    }
    __syncthreads();

    int excl = s_excl + incl - v;
    if (i < NNODES) {
        g_rowptr[i] = excl;
        g_rowcur[i] = excl;
        if (i == NNODES - 1) g_rowptr[NNODES] = excl + v;
    }
}

// ---------------------------------------------------------------------------
__global__ void scatter_kernel(const float* __restrict__ eval,
                               const int*   __restrict__ erow,
                               const int*   __restrict__ ecol,
                               int nnz) {
    int i = (blockIdx.x * blockDim.x + threadIdx.x) * 4;
    if (i + 3 < nnz) {
        int4   r = *reinterpret_cast<const int4*>(erow + i);
        int4   c = *reinterpret_cast<const int4*>(ecol + i);
        float4 v = *reinterpret_cast<const float4*>(eval + i);
        int p0 = atomicAdd(&g_rowcur[r.x], 1);
        int p1 = atomicAdd(&g_rowcur[r.y], 1);
        int p2 = atomicAdd(&g_rowcur[r.z], 1);
        int p3 = atomicAdd(&g_rowcur[r.w], 1);
        g_csr[p0] = make_int2(c.x, __float_as_int(v.x));
        g_csr[p1] = make_int2(c.y, __float_as_int(v.y));
        g_csr[p2] = make_int2(c.z, __float_as_int(v.z));
        g_csr[p3] = make_int2(c.w, __float_as_int(v.w));
    } else {
        for (int j = i; j < nnz; j++) {
            int pos = atomicAdd(&g_rowcur[erow[j]], 1);
            g_csr[pos] = make_int2(ecol[j], __float_as_int(eval[j]));
        }
    }
}

// ---------------------------------------------------------------------------
// SpMM-CSR, warp per row, fp16 gathers, fp32 accumulate, fp16 outputs.
// ---------------------------------------------------------------------------
__global__ __launch_bounds__(256)
void spmm1_csr_kernel() {
    int row = blockIdx.x * (blockDim.x >> 5) + (threadIdx.x >> 5);
    if (row >= NNODES) return;
    int lane = threadIdx.x & 31;
    int beg = g_rowptr[row];
    int end = g_rowptr[row + 1];

    float4 acc = make_float4(0.f, 0.f, 0.f, 0.f);
    for (int base = beg; base < end; base += 32) {
        int cnt = min(32, end - base);
        int   mycol = 0;
        float myval = 0.f;
        if (lane < cnt) {
            int2 e = g_csr[base + lane];
            mycol = e.x;
            myval = __int_as_float(e.y);
        }
        #pragma unroll 8
        for (int j = 0; j < cnt; j++) {
            int   c = __shfl_sync(0xffffffffu, mycol, j);
            float v = __shfl_sync(0xffffffffu, myval, j);
            uint2 h = *reinterpret_cast<const uint2*>(
                          g_featH + (size_t)c * FDIM + lane * 4);
            float2 f0 = __half22float2(*reinterpret_cast<__half2*>(&h.x));
            float2 f1 = __half22float2(*reinterpret_cast<__half2*>(&h.y));
            acc.x = fmaf(v, f0.x, acc.x);
            acc.y = fmaf(v, f0.y, acc.y);
            acc.z = fmaf(v, f1.x, acc.z);
            acc.w = fmaf(v, f1.y, acc.w);
        }
    }
    uint2 hf = *reinterpret_cast<const uint2*>(
                   g_featH + (size_t)row * FDIM + lane * 4);
    float2 t0 = __half22float2(*reinterpret_cast<__half2*>(&hf.x));
    float2 t1 = __half22float2(*reinterpret_cast<__half2*>(&hf.y));

    __half2 l0 = __floats2half2_rn(acc.x + t0.x, acc.y + t0.y);
    __half2 l1 = __floats2half2_rn(acc.z + t1.x, acc.w + t1.y);
    uint2 stl = make_uint2(*reinterpret_cast<uint32_t*>(&l0),
                           *reinterpret_cast<uint32_t*>(&l1));
    *reinterpret_cast<uint2*>(g_LfPH + (size_t)row * FDIM + lane * 4) = stl;

    __half2 p0 = __floats2half2_rn(acc.x * t0.x, acc.y * t0.y);
    __half2 p1 = __floats2half2_rn(acc.z * t1.x, acc.w * t1.y);
    uint2 stp = make_uint2(*reinterpret_cast<uint32_t*>(&p0),
                           *reinterpret_cast<uint32_t*>(&p1));
    *reinterpret_cast<uint2*>(g_PH + (size_t)row * FDIM + lane * 4) = stp;
}

__global__ __launch_bounds__(256)
void spmm2_csr_kernel() {
    int row = blockIdx.x * (blockDim.x >> 5) + (threadIdx.x >> 5);
    if (row >= NNODES) return;
    int lane = threadIdx.x & 31;
    int beg = g_rowptr[row];
    int end = g_rowptr[row + 1];

    float4 acc = make_float4(0.f, 0.f, 0.f, 0.f);
    for (int base = beg; base < end; base += 32) {
        int cnt = min(32, end - base);
        int   mycol = 0;
        float myval = 0.f;
        if (lane < cnt) {
            int2 e = g_csr[base + lane];
            mycol = e.x;
            myval = __int_as_float(e.y);
        }
        #pragma unroll 8
        for (int j = 0; j < cnt; j++) {
            int   c = __shfl_sync(0xffffffffu, mycol, j);
            float v = __shfl_sync(0xffffffffu, myval, j);
            uint2 h = *reinterpret_cast<const uint2*>(
                          g_PH + (size_t)c * FDIM + lane * 4);
            float2 f0 = __half22float2(*reinterpret_cast<__half2*>(&h.x));
            float2 f1 = __half22float2(*reinterpret_cast<__half2*>(&h.y));
            acc.x = fmaf(v, f0.x, acc.x);
            acc.y = fmaf(v, f0.y, acc.y);
            acc.z = fmaf(v, f1.x, acc.z);
            acc.w = fmaf(v, f1.y, acc.w);
        }
    }
    __half2 l0 = __floats2half2_rn(acc.x, acc.y);
    __half2 l1 = __floats2half2_rn(acc.z, acc.w);
    uint2 st = make_uint2(*reinterpret_cast<uint32_t*>(&l0),
                          *reinterpret_cast<uint32_t*>(&l1));
    *reinterpret_cast<uint2*>(g_LiH + (size_t)row * FDIM + lane * 4) = st;
}

// ---------------------------------------------------------------------------
// Persistent tensor-core GEMM (mma.sync m16n8k16 fp16, fp32 accum):
//   out = [LfPH ; LiH] (N x 256) @ [W1 ; W2] (256 x 128) + (b1+b2)
// ---------------------------------------------------------------------------
#define WTH 264
#define ASH 136
#define OFF_WT 0
#define OFF_AS (128 * WTH * 2)                       // 67584
#define OFF_BI (OFF_AS + 128 * ASH * 2)              // 102400
#define SMEM_GEMM (OFF_BI + 512)                     // 102912

static __device__ __forceinline__ void mma16(float* d,
                                             uint32_t a0, uint32_t a1,
                                             uint32_t a2, uint32_t a3,
                                             uint32_t b0, uint32_t b1) {
    asm volatile(
        "mma.sync.aligned.m16n8k16.row.col.f32.f16.f16.f32 "
        "{%0,%1,%2,%3}, {%4,%5,%6,%7}, {%8,%9}, {%0,%1,%2,%3};"
        : "+f"(d[0]), "+f"(d[1]), "+f"(d[2]), "+f"(d[3])
        : "r"(a0), "r"(a1), "r"(a2), "r"(a3), "r"(b0), "r"(b1));
}

__global__ __launch_bounds__(256)
void gemm_mma_kernel(const float* __restrict__ W1,
                     const float* __restrict__ b1,
                     const float* __restrict__ W2,
                     const float* __restrict__ b2,
                     float* __restrict__ out) {
    extern __shared__ char smem[];
    __half* Wt   = reinterpret_cast<__half*>(smem + OFF_WT);  // [128][264]
    __half* As   = reinterpret_cast<__half*>(smem + OFF_AS);  // [128][136]
    float*  bias = reinterpret_cast<float*>(smem + OFF_BI);

    const int tid  = threadIdx.x;
    const int w    = tid >> 5;
    const int lane = tid & 31;
    const int tg   = lane & 3;
    const int gid  = lane >> 2;
    const int wm   = w & 3;
    const int colg = w >> 2;

    // ---- stage Wt[n][k] = fp16(W[k][n]) ONCE (k = 0..255) ----
    #pragma unroll
    for (int it = 0; it < 32; it++) {
        int wt = it * 8 + w;
        int k0 = (wt >> 2) * 4;
        int n  = (wt & 3) * 32 + lane;
        const float* Wsrc = (k0 < 128) ? (W1 + (size_t)k0 * 128)
                                       : (W2 + (size_t)(k0 - 128) * 128);
        __half2 h01 = __floats2half2_rn(Wsrc[0 * 128 + n], Wsrc[1 * 128 + n]);
        __half2 h23 = __floats2half2_rn(Wsrc[2 * 128 + n], Wsrc[3 * 128 + n]);
        uint2 st = make_uint2(*reinterpret_cast<uint32_t*>(&h01),
                              *reinterpret_cast<uint32_t*>(&h23));
        *reinterpret_cast<uint2*>(Wt + n * WTH + k0) = st;
    }
    if (tid < 128) bias[tid] = b1[tid] + b2[tid];

    for (int tile = blockIdx.x; tile < NTILES; tile += gridDim.x) {
        const int row0 = tile * 128;

        float acc[2][8][4];
        #pragma unroll
        for (int s = 0; s < 2; s++)
            #pragma unroll
            for (int nt = 0; nt < 8; nt++)
                #pragma unroll
                for (int q = 0; q < 4; q++) acc[s][nt][q] = 0.f;

        #pragma unroll
        for (int phase = 0; phase < 2; phase++) {
            const __half* src = phase ? g_LiH : g_LfPH;
            __syncthreads();

            #pragma unroll
            for (int it = 0; it < 8; it++) {
                int idx = it * 256 + tid;
                int r = idx >> 4;
                int j = idx & 15;
                int row = row0 + r;
                if (row >= NNODES) row = NNODES - 1;
                uint4 v = reinterpret_cast<const uint4*>(
                              src + (size_t)row * FDIM)[j];
                *reinterpret_cast<uint4*>(As + r * ASH + j * 8) = v;
            }
            __syncthreads();

            const int kg0 = phase * 128;
            #pragma unroll 2
            for (int kb = 0; kb < 128; kb += 16) {
                uint32_t a[2][4];
                #pragma unroll
                for (int sub = 0; sub < 2; sub++) {
                    int rb = wm * 32 + sub * 16 + gid;
                    const __half* ap0 = As + rb * ASH + kb + 2 * tg;
                    const __half* ap1 = As + (rb + 8) * ASH + kb + 2 * tg;
                    a[sub][0] = *reinterpret_cast<const uint32_t*>(ap0);
                    a[sub][1] = *reinterpret_cast<const uint32_t*>(ap1);
                    a[sub][2] = *reinterpret_cast<const uint32_t*>(ap0 + 8);
                    a[sub][3] = *reinterpret_cast<const uint32_t*>(ap1 + 8);
                }
                #pragma unroll
                for (int nt = 0; nt < 8; nt++) {
                    int n = colg * 64 + nt * 8 + gid;
                    const __half* bp = Wt + n * WTH + kg0 + kb + 2 * tg;
                    uint32_t b0 = *reinterpret_cast<const uint32_t*>(bp);
                    uint32_t b1 = *reinterpret_cast<const uint32_t*>(bp + 8);
                    mma16(acc[0][nt], a[0][0], a[0][1], a[0][2], a[0][3], b0, b1);
                    mma16(acc[1][nt], a[1][0], a[1][1], a[1][2], a[1][3], b0, b1);
                }
            }
        }

        #pragma unroll
        for (int sub = 0; sub < 2; sub++) {
            int r0 = row0 + wm * 32 + sub * 16 + gid;
            #pragma unroll
            for (int nt = 0; nt < 8; nt++) {
                int c = colg * 64 + nt * 8 + tg * 2;
                float bx = bias[c], by = bias[c + 1];
                if (r0 < NNODES) {
                    float2 o = make_float2(acc[sub][nt][0] + bx, acc[sub][nt][1] + by);
                    *reinterpret_cast<float2*>(out + (size_t)r0 * FDIM + c) = o;
                }
                if (r0 + 8 < NNODES) {
                    float2 o = make_float2(acc[sub][nt][2] + bx, acc[sub][nt][3] + by);
                    *reinterpret_cast<float2*>(out + (size_t)(r0 + 8) * FDIM + c) = o;
                }
            }
        }
    }
}

// ---------------------------------------------------------------------------
extern "C" void kernel_launch(void* const* d_in, const int* in_sizes, int n_in,
                              void* d_out, int out_size) {
    const float* feat = (const float*)d_in[0];
    const float* eval = (const float*)d_in[1];
    const float* W1   = (const float*)d_in[2];
    const float* b1   = (const float*)d_in[3];
    const float* W2   = (const float*)d_in[4];
    const float* b2   = (const float*)d_in[5];
    const int*   erow = (const int*)d_in[6];
    const int*   ecol = (const int*)d_in[7];
    float*       out  = (float*)d_out;

    const int nnz = in_sizes[1];

    // zero row counts (graph memset node)
    {
        void* p = nullptr;
        cudaGetSymbolAddress(&p, g_rowcnt);
        cudaMemsetAsync(p, 0, NNODES * sizeof(int));
    }

    // fused: fp16 feature copy || histogram || scan-flag clear
    {
        int cvt_blocks  = (int)(((size_t)NNODES * FDIM / 8 + 255) / 256);  // 6250
        int hist_blocks = (nnz / 4 + 255) / 256;
        fused_cvt_hist_kernel<<<cvt_blocks + hist_blocks + 1, 256>>>(
            feat, erow, nnz, cvt_blocks, hist_blocks);
    }

    // single-kernel decoupled-lookback scan
    scan_lookback_kernel<<<SCAN_G, SCAN_B>>>();

    // scatter into CSR
    scatter_kernel<<<(nnz / 4 + 255) / 256, 256>>>(eval, erow, ecol, nnz);

    // SpMM passes (warp per row, fp16 gathers + fp16 outputs)
    {
        int blocks = (NNODES + 7) / 8;
        spmm1_csr_kernel<<<blocks, 256>>>();
        spmm2_csr_kernel<<<blocks, 256>>>();
    }

    // GEMM (persistent, mma.sync fp16 m16n8k16, 2 CTAs/SM)
    {
        cudaFuncSetAttribute(gemm_mma_kernel,
                             cudaFuncAttributeMaxDynamicSharedMemorySize,
                             SMEM_GEMM);
        gemm_mma_kernel<<<296, 256, SMEM_GEMM>>>(W1, b1, W2, b2, out);
    }
}

// round 12
// speedup vs baseline: 1.0575x; 1.0575x over previous
#include <cuda_runtime.h>
#include <cuda_fp16.h>
#include <cstdint>

#define NNODES 100000
#define FDIM   128
#define NTILES ((NNODES + 127) / 128)

// ---- device-global scratch (allocations forbidden) ----
__device__ __half g_LfPH[(size_t)NNODES * FDIM]; // Lf + feat  fp16 (GEMM A, k 0..127)
__device__ __half g_LiH [(size_t)NNODES * FDIM]; // A @ P      fp16 (GEMM A, k 128..255)
__device__ __half g_featH[(size_t)NNODES * FDIM];// fp16 copy of features
__device__ __half g_PH  [(size_t)NNODES * FDIM]; // Lf * feat fp16 (spmm2 input)
__device__ int    g_rowcnt[NNODES];
__device__ int    g_rowptr[NNODES + 1];
__device__ int    g_epos[1600000 + 1024];        // per-edge slot within its row
__device__ int2   g_csr[1600000 + 1024];         // (col, float_bits(val)) packed

#define SCAN_B 1024
#define SCAN_G ((NNODES + SCAN_B - 1) / SCAN_B)  // 98
// decoupled-lookback state: low 32 = value, high 32 = flag (1=aggregate, 2=prefix)
__device__ unsigned long long g_scanpkt[SCAN_G];

// ---------------------------------------------------------------------------
// hist: count edges per row AND record each edge's slot within its row
// (atomicAdd return value). Last block clears scan flags.
// ---------------------------------------------------------------------------
__global__ void hist_kernel(const int* __restrict__ erow, int nnz,
                            int hist_blocks) {
    int b = blockIdx.x;
    if (b < hist_blocks) {
        int i = (b * blockDim.x + threadIdx.x) * 4;
        if (i + 3 < nnz) {
            int4 r = *reinterpret_cast<const int4*>(erow + i);
            int4 p;
            p.x = atomicAdd(&g_rowcnt[r.x], 1);
            p.y = atomicAdd(&g_rowcnt[r.y], 1);
            p.z = atomicAdd(&g_rowcnt[r.z], 1);
            p.w = atomicAdd(&g_rowcnt[r.w], 1);
            *reinterpret_cast<int4*>(g_epos + i) = p;
        } else {
            for (int j = i; j < nnz; j++)
                g_epos[j] = atomicAdd(&g_rowcnt[erow[j]], 1);
        }
    } else {
        if (threadIdx.x < SCAN_G) g_scanpkt[threadIdx.x] = 0ull;
    }
}

// ---------------------------------------------------------------------------
// Single-kernel exclusive scan (decoupled lookback, 98 co-resident blocks).
// ---------------------------------------------------------------------------
__global__ __launch_bounds__(SCAN_B, 1)
void scan_lookback_kernel() {
    __shared__ int s[SCAN_B];
    __shared__ int s_excl;
    const int tid = threadIdx.x;
    const int b   = blockIdx.x;
    const int i   = b * SCAN_B + tid;
    int v = (i < NNODES) ? g_rowcnt[i] : 0;

    s[tid] = v;
    __syncthreads();
    for (int off = 1; off < SCAN_B; off <<= 1) {
        int t = (tid >= off) ? s[tid - off] : 0;
        __syncthreads();
        s[tid] += t;
        __syncthreads();
    }
    int incl  = s[tid];
    int total = s[SCAN_B - 1];

    if (tid == 0) {
        volatile unsigned long long* pkt = g_scanpkt;
        if (b == 0) {
            pkt[0] = ((unsigned long long)2 << 32) | (unsigned int)total;
            s_excl = 0;
        } else {
            pkt[b] = ((unsigned long long)1 << 32) | (unsigned int)total;
            int excl = 0;
            for (int j = b - 1; j >= 0; ) {
                unsigned long long p;
                do { p = pkt[j]; } while ((p >> 32) == 0ull);
                excl += (int)(unsigned int)p;
                if ((p >> 32) == 2ull) break;
                j--;
            }
            pkt[b] = ((unsigned long long)2 << 32) | (unsigned int)(excl + total);
            s_excl = excl;
        }
    }
    __syncthreads();

    int excl = s_excl + incl - v;
    if (i < NNODES) {
        g_rowptr[i] = excl;
        if (i == NNODES - 1) g_rowptr[NNODES] = excl + v;
    }
}

// ---------------------------------------------------------------------------
// Fused: [scat blocks] atomic-free CSR scatter | [cvt blocks] feat->fp16 copy
// ---------------------------------------------------------------------------
__global__ void fused_scatter_cvt_kernel(const float* __restrict__ eval,
                                         const int*   __restrict__ erow,
                                         const int*   __restrict__ ecol,
                                         const float* __restrict__ feat,
                                         int nnz, int scat_blocks) {
    int b = blockIdx.x;
    if (b < scat_blocks) {
        int i = (b * blockDim.x + threadIdx.x) * 4;
        if (i + 3 < nnz) {
            int4   r = *reinterpret_cast<const int4*>(erow + i);
            int4   c = *reinterpret_cast<const int4*>(ecol + i);
            int4   p = *reinterpret_cast<const int4*>(g_epos + i);
            float4 v = *reinterpret_cast<const float4*>(eval + i);
            g_csr[g_rowptr[r.x] + p.x] = make_int2(c.x, __float_as_int(v.x));
            g_csr[g_rowptr[r.y] + p.y] = make_int2(c.y, __float_as_int(v.y));
            g_csr[g_rowptr[r.z] + p.z] = make_int2(c.z, __float_as_int(v.z));
            g_csr[g_rowptr[r.w] + p.w] = make_int2(c.w, __float_as_int(v.w));
        } else {
            for (int j = i; j < nnz; j++)
                g_csr[g_rowptr[erow[j]] + g_epos[j]] =
                    make_int2(ecol[j], __float_as_int(eval[j]));
        }
    } else {
        size_t i = (size_t)(b - scat_blocks) * blockDim.x + threadIdx.x;
        const size_t total = (size_t)NNODES * FDIM / 8;
        if (i < total) {
            const float4* s = reinterpret_cast<const float4*>(feat) + i * 2;
            float4 a = s[0], bb = s[1];
            __half2 h0 = __floats2half2_rn(a.x, a.y);
            __half2 h1 = __floats2half2_rn(a.z, a.w);
            __half2 h2 = __floats2half2_rn(bb.x, bb.y);
            __half2 h3 = __floats2half2_rn(bb.z, bb.w);
            uint4 st = make_uint4(*reinterpret_cast<uint32_t*>(&h0),
                                  *reinterpret_cast<uint32_t*>(&h1),
                                  *reinterpret_cast<uint32_t*>(&h2),
                                  *reinterpret_cast<uint32_t*>(&h3));
            reinterpret_cast<uint4*>(g_featH)[i] = st;
        }
    }
}

// ---------------------------------------------------------------------------
// SpMM-CSR, warp per row; uniform-LDG edge fetch (warp broadcast, L1 hit),
// fp16 gathers, fp32 accumulate, fp16 outputs.
// ---------------------------------------------------------------------------
__global__ __launch_bounds__(256)
void spmm1_csr_kernel() {
    int row = blockIdx.x * (blockDim.x >> 5) + (threadIdx.x >> 5);
    if (row >= NNODES) return;
    int lane = threadIdx.x & 31;
    int beg = g_rowptr[row];
    int end = g_rowptr[row + 1];

    float4 acc = make_float4(0.f, 0.f, 0.f, 0.f);
    #pragma unroll 4
    for (int e = beg; e < end; e++) {
        int2  ed = g_csr[e];                 // same addr warp-wide: broadcast
        float v  = __int_as_float(ed.y);
        uint2 h = *reinterpret_cast<const uint2*>(
                      g_featH + (size_t)ed.x * FDIM + lane * 4);
        float2 f0 = __half22float2(*reinterpret_cast<__half2*>(&h.x));
        float2 f1 = __half22float2(*reinterpret_cast<__half2*>(&h.y));
        acc.x = fmaf(v, f0.x, acc.x);
        acc.y = fmaf(v, f0.y, acc.y);
        acc.z = fmaf(v, f1.x, acc.z);
        acc.w = fmaf(v, f1.y, acc.w);
    }
    uint2 hf = *reinterpret_cast<const uint2*>(
                   g_featH + (size_t)row * FDIM + lane * 4);
    float2 t0 = __half22float2(*reinterpret_cast<__half2*>(&hf.x));
    float2 t1 = __half22float2(*reinterpret_cast<__half2*>(&hf.y));

    __half2 l0 = __floats2half2_rn(acc.x + t0.x, acc.y + t0.y);
    __half2 l1 = __floats2half2_rn(acc.z + t1.x, acc.w + t1.y);
    uint2 stl = make_uint2(*reinterpret_cast<uint32_t*>(&l0),
                           *reinterpret_cast<uint32_t*>(&l1));
    *reinterpret_cast<uint2*>(g_LfPH + (size_t)row * FDIM + lane * 4) = stl;

    __half2 p0 = __floats2half2_rn(acc.x * t0.x, acc.y * t0.y);
    __half2 p1 = __floats2half2_rn(acc.z * t1.x, acc.w * t1.y);
    uint2 stp = make_uint2(*reinterpret_cast<uint32_t*>(&p0),
                           *reinterpret_cast<uint32_t*>(&p1));
    *reinterpret_cast<uint2*>(g_PH + (size_t)row * FDIM + lane * 4) = stp;
}

__global__ __launch_bounds__(256)
void spmm2_csr_kernel() {
    int row = blockIdx.x * (blockDim.x >> 5) + (threadIdx.x >> 5);
    if (row >= NNODES) return;
    int lane = threadIdx.x & 31;
    int beg = g_rowptr[row];
    int end = g_rowptr[row + 1];

    float4 acc = make_float4(0.f, 0.f, 0.f, 0.f);
    #pragma unroll 4
    for (int e = beg; e < end; e++) {
        int2  ed = g_csr[e];
        float v  = __int_as_float(ed.y);
        uint2 h = *reinterpret_cast<const uint2*>(
                      g_PH + (size_t)ed.x * FDIM + lane * 4);
        float2 f0 = __half22float2(*reinterpret_cast<__half2*>(&h.x));
        float2 f1 = __half22float2(*reinterpret_cast<__half2*>(&h.y));
        acc.x = fmaf(v, f0.x, acc.x);
        acc.y = fmaf(v, f0.y, acc.y);
        acc.z = fmaf(v, f1.x, acc.z);
        acc.w = fmaf(v, f1.y, acc.w);
    }
    __half2 l0 = __floats2half2_rn(acc.x, acc.y);
    __half2 l1 = __floats2half2_rn(acc.z, acc.w);
    uint2 st = make_uint2(*reinterpret_cast<uint32_t*>(&l0),
                          *reinterpret_cast<uint32_t*>(&l1));
    *reinterpret_cast<uint2*>(g_LiH + (size_t)row * FDIM + lane * 4) = st;
}

// ---------------------------------------------------------------------------
// Persistent tensor-core GEMM (mma.sync m16n8k16 fp16, fp32 accum):
//   out = [LfPH ; LiH] (N x 256) @ [W1 ; W2] (256 x 128) + (b1+b2)
// ---------------------------------------------------------------------------
#define WTH 264
#define ASH 136
#define OFF_WT 0
#define OFF_AS (128 * WTH * 2)                       // 67584
#define OFF_BI (OFF_AS + 128 * ASH * 2)              // 102400
#define SMEM_GEMM (OFF_BI + 512)                     // 102912

static __device__ __forceinline__ void mma16(float* d,
                                             uint32_t a0, uint32_t a1,
                                             uint32_t a2, uint32_t a3,
                                             uint32_t b0, uint32_t b1) {
    asm volatile(
        "mma.sync.aligned.m16n8k16.row.col.f32.f16.f16.f32 "
        "{%0,%1,%2,%3}, {%4,%5,%6,%7}, {%8,%9}, {%0,%1,%2,%3};"
        : "+f"(d[0]), "+f"(d[1]), "+f"(d[2]), "+f"(d[3])
        : "r"(a0), "r"(a1), "r"(a2), "r"(a3), "r"(b0), "r"(b1));
}

__global__ __launch_bounds__(256)
void gemm_mma_kernel(const float* __restrict__ W1,
                     const float* __restrict__ b1,
                     const float* __restrict__ W2,
                     const float* __restrict__ b2,
                     float* __restrict__ out) {
    extern __shared__ char smem[];
    __half* Wt   = reinterpret_cast<__half*>(smem + OFF_WT);  // [128][264]
    __half* As   = reinterpret_cast<__half*>(smem + OFF_AS);  // [128][136]
    float*  bias = reinterpret_cast<float*>(smem + OFF_BI);

    const int tid  = threadIdx.x;
    const int w    = tid >> 5;
    const int lane = tid & 31;
    const int tg   = lane & 3;
    const int gid  = lane >> 2;
    const int wm   = w & 3;
    const int colg = w >> 2;

    #pragma unroll
    for (int it = 0; it < 32; it++) {
        int wt = it * 8 + w;
        int k0 = (wt >> 2) * 4;
        int n  = (wt & 3) * 32 + lane;
        const float* Wsrc = (k0 < 128) ? (W1 + (size_t)k0 * 128)
                                       : (W2 + (size_t)(k0 - 128) * 128);
        __half2 h01 = __floats2half2_rn(Wsrc[0 * 128 + n], Wsrc[1 * 128 + n]);
        __half2 h23 = __floats2half2_rn(Wsrc[2 * 128 + n], Wsrc[3 * 128 + n]);
        uint2 st = make_uint2(*reinterpret_cast<uint32_t*>(&h01),
                              *reinterpret_cast<uint32_t*>(&h23));
        *reinterpret_cast<uint2*>(Wt + n * WTH + k0) = st;
    }
    if (tid < 128) bias[tid] = b1[tid] + b2[tid];

    for (int tile = blockIdx.x; tile < NTILES; tile += gridDim.x) {
        const int row0 = tile * 128;

        float acc[2][8][4];
        #pragma unroll
        for (int s = 0; s < 2; s++)
            #pragma unroll
            for (int nt = 0; nt < 8; nt++)
                #pragma unroll
                for (int q = 0; q < 4; q++) acc[s][nt][q] = 0.f;

        #pragma unroll
        for (int phase = 0; phase < 2; phase++) {
            const __half* src = phase ? g_LiH : g_LfPH;
            __syncthreads();

            #pragma unroll
            for (int it = 0; it < 8; it++) {
                int idx = it * 256 + tid;
                int r = idx >> 4;
                int j = idx & 15;
                int row = row0 + r;
                if (row >= NNODES) row = NNODES - 1;
                uint4 v = reinterpret_cast<const uint4*>(
                              src + (size_t)row * FDIM)[j];
                *reinterpret_cast<uint4*>(As + r * ASH + j * 8) = v;
            }
            __syncthreads();

            const int kg0 = phase * 128;
            #pragma unroll 2
            for (int kb = 0; kb < 128; kb += 16) {
                uint32_t a[2][4];
                #pragma unroll
                for (int sub = 0; sub < 2; sub++) {
                    int rb = wm * 32 + sub * 16 + gid;
                    const __half* ap0 = As + rb * ASH + kb + 2 * tg;
                    const __half* ap1 = As + (rb + 8) * ASH + kb + 2 * tg;
                    a[sub][0] = *reinterpret_cast<const uint32_t*>(ap0);
                    a[sub][1] = *reinterpret_cast<const uint32_t*>(ap1);
                    a[sub][2] = *reinterpret_cast<const uint32_t*>(ap0 + 8);
                    a[sub][3] = *reinterpret_cast<const uint32_t*>(ap1 + 8);
                }
                #pragma unroll
                for (int nt = 0; nt < 8; nt++) {
                    int n = colg * 64 + nt * 8 + gid;
                    const __half* bp = Wt + n * WTH + kg0 + kb + 2 * tg;
                    uint32_t b0 = *reinterpret_cast<const uint32_t*>(bp);
                    uint32_t b1 = *reinterpret_cast<const uint32_t*>(bp + 8);
                    mma16(acc[0][nt], a[0][0], a[0][1], a[0][2], a[0][3], b0, b1);
                    mma16(acc[1][nt], a[1][0], a[1][1], a[1][2], a[1][3], b0, b1);
                }
            }
        }

        #pragma unroll
        for (int sub = 0; sub < 2; sub++) {
            int r0 = row0 + wm * 32 + sub * 16 + gid;
            #pragma unroll
            for (int nt = 0; nt < 8; nt++) {
                int c = colg * 64 + nt * 8 + tg * 2;
                float bx = bias[c], by = bias[c + 1];
                if (r0 < NNODES) {
                    float2 o = make_float2(acc[sub][nt][0] + bx, acc[sub][nt][1] + by);
                    *reinterpret_cast<float2*>(out + (size_t)r0 * FDIM + c) = o;
                }
                if (r0 + 8 < NNODES) {
                    float2 o = make_float2(acc[sub][nt][2] + bx, acc[sub][nt][3] + by);
                    *reinterpret_cast<float2*>(out + (size_t)(r0 + 8) * FDIM + c) = o;
                }
            }
        }
    }
}

// ---------------------------------------------------------------------------
extern "C" void kernel_launch(void* const* d_in, const int* in_sizes, int n_in,
                              void* d_out, int out_size) {
    const float* feat = (const float*)d_in[0];
    const float* eval = (const float*)d_in[1];
    const float* W1   = (const float*)d_in[2];
    const float* b1   = (const float*)d_in[3];
    const float* W2   = (const float*)d_in[4];
    const float* b2   = (const float*)d_in[5];
    const int*   erow = (const int*)d_in[6];
    const int*   ecol = (const int*)d_in[7];
    float*       out  = (float*)d_out;

    const int nnz = in_sizes[1];

    // zero row counts (graph memset node)
    {
        void* p = nullptr;
        cudaGetSymbolAddress(&p, g_rowcnt);
        cudaMemsetAsync(p, 0, NNODES * sizeof(int));
    }

    // hist (+ per-edge slot assignment) + scan-flag clear
    {
        int hist_blocks = (nnz / 4 + 255) / 256;
        hist_kernel<<<hist_blocks + 1, 256>>>(erow, nnz, hist_blocks);
    }

    // single-kernel decoupled-lookback scan
    scan_lookback_kernel<<<SCAN_G, SCAN_B>>>();

    // fused: atomic-free scatter || fp16 feature copy
    {
        int scat_blocks = (nnz / 4 + 255) / 256;
        int cvt_blocks  = (int)(((size_t)NNODES * FDIM / 8 + 255) / 256);
        fused_scatter_cvt_kernel<<<scat_blocks + cvt_blocks, 256>>>(
            eval, erow, ecol, feat, nnz, scat_blocks);
    }

    // SpMM passes (warp per row, fp16 gathers + fp16 outputs)
    {
        int blocks = (NNODES + 7) / 8;
        spmm1_csr_kernel<<<blocks, 256>>>();
        spmm2_csr_kernel<<<blocks, 256>>>();
    }

    // GEMM (persistent, mma.sync fp16 m16n8k16, 2 CTAs/SM)
    {
        cudaFuncSetAttribute(gemm_mma_kernel,
                             cudaFuncAttributeMaxDynamicSharedMemorySize,
                             SMEM_GEMM);
        gemm_mma_kernel<<<296, 256, SMEM_GEMM>>>(W1, b1, W2, b2, out);
    }
}

// round 13
// speedup vs baseline: 1.1103x; 1.0499x over previous
#include <cuda_runtime.h>
#include <cuda_fp16.h>
#include <cstdint>

#define NNODES 100000
#define FDIM   128
#define NTILES ((NNODES + 127) / 128)

// ---- device-global scratch (allocations forbidden) ----
__device__ __half g_LfPH[(size_t)NNODES * FDIM]; // Lf + feat  fp16 (GEMM A, k 0..127)
__device__ __half g_LiH [(size_t)NNODES * FDIM]; // A @ P      fp16 (GEMM A, k 128..255)
__device__ __half g_featH[(size_t)NNODES * FDIM];// fp16 copy of features
__device__ __half g_PH  [(size_t)NNODES * FDIM]; // Lf * feat fp16 (spmm2 input)
__device__ int    g_rowcnt[NNODES];
__device__ int    g_rowptr[NNODES + 1];
__device__ int    g_epos[1600000 + 1024];        // per-edge slot within its row
__device__ int2   g_csr[1600000 + 1024];         // (col*256 byte-off, float_bits(val))

#define SCAN_B 1024
#define SCAN_G ((NNODES + SCAN_B - 1) / SCAN_B)  // 98
// decoupled-lookback state: low 32 = value, high 32 = flag (1=aggregate, 2=prefix)
__device__ unsigned long long g_scanpkt[SCAN_G];

// ---------------------------------------------------------------------------
// hist: count edges per row AND record each edge's slot within its row.
// Last block clears scan flags.
// ---------------------------------------------------------------------------
__global__ void hist_kernel(const int* __restrict__ erow, int nnz,
                            int hist_blocks) {
    int b = blockIdx.x;
    if (b < hist_blocks) {
        int i = (b * blockDim.x + threadIdx.x) * 4;
        if (i + 3 < nnz) {
            int4 r = *reinterpret_cast<const int4*>(erow + i);
            int4 p;
            p.x = atomicAdd(&g_rowcnt[r.x], 1);
            p.y = atomicAdd(&g_rowcnt[r.y], 1);
            p.z = atomicAdd(&g_rowcnt[r.z], 1);
            p.w = atomicAdd(&g_rowcnt[r.w], 1);
            *reinterpret_cast<int4*>(g_epos + i) = p;
        } else {
            for (int j = i; j < nnz; j++)
                g_epos[j] = atomicAdd(&g_rowcnt[erow[j]], 1);
        }
    } else {
        if (threadIdx.x < SCAN_G) g_scanpkt[threadIdx.x] = 0ull;
    }
}

// ---------------------------------------------------------------------------
// Single-kernel exclusive scan (decoupled lookback, 98 co-resident blocks).
// ---------------------------------------------------------------------------
__global__ __launch_bounds__(SCAN_B, 1)
void scan_lookback_kernel() {
    __shared__ int s[SCAN_B];
    __shared__ int s_excl;
    const int tid = threadIdx.x;
    const int b   = blockIdx.x;
    const int i   = b * SCAN_B + tid;
    int v = (i < NNODES) ? g_rowcnt[i] : 0;

    s[tid] = v;
    __syncthreads();
    for (int off = 1; off < SCAN_B; off <<= 1) {
        int t = (tid >= off) ? s[tid - off] : 0;
        __syncthreads();
        s[tid] += t;
        __syncthreads();
    }
    int incl  = s[tid];
    int total = s[SCAN_B - 1];

    if (tid == 0) {
        volatile unsigned long long* pkt = g_scanpkt;
        if (b == 0) {
            pkt[0] = ((unsigned long long)2 << 32) | (unsigned int)total;
            s_excl = 0;
        } else {
            pkt[b] = ((unsigned long long)1 << 32) | (unsigned int)total;
            int excl = 0;
            for (int j = b - 1; j >= 0; ) {
                unsigned long long p;
                do { p = pkt[j]; } while ((p >> 32) == 0ull);
                excl += (int)(unsigned int)p;
                if ((p >> 32) == 2ull) break;
                j--;
            }
            pkt[b] = ((unsigned long long)2 << 32) | (unsigned int)(excl + total);
            s_excl = excl;
        }
    }
    __syncthreads();

    int excl = s_excl + incl - v;
    if (i < NNODES) {
        g_rowptr[i] = excl;
        if (i == NNODES - 1) g_rowptr[NNODES] = excl + v;
    }
}

// ---------------------------------------------------------------------------
// Fused: [scat blocks] atomic-free CSR scatter | [cvt blocks] feat->fp16 copy
// Scatter stores (col*256, val_bits): col pre-scaled to byte offset.
// ---------------------------------------------------------------------------
__global__ void fused_scatter_cvt_kernel(const float* __restrict__ eval,
                                         const int*   __restrict__ erow,
                                         const int*   __restrict__ ecol,
                                         const float* __restrict__ feat,
                                         int nnz, int scat_blocks) {
    int b = blockIdx.x;
    if (b < scat_blocks) {
        int i = (b * blockDim.x + threadIdx.x) * 4;
        if (i + 3 < nnz) {
            int4   r = *reinterpret_cast<const int4*>(erow + i);
            int4   c = *reinterpret_cast<const int4*>(ecol + i);
            int4   p = *reinterpret_cast<const int4*>(g_epos + i);
            float4 v = *reinterpret_cast<const float4*>(eval + i);
            g_csr[g_rowptr[r.x] + p.x] = make_int2(c.x << 8, __float_as_int(v.x));
            g_csr[g_rowptr[r.y] + p.y] = make_int2(c.y << 8, __float_as_int(v.y));
            g_csr[g_rowptr[r.z] + p.z] = make_int2(c.z << 8, __float_as_int(v.z));
            g_csr[g_rowptr[r.w] + p.w] = make_int2(c.w << 8, __float_as_int(v.w));
        } else {
            for (int j = i; j < nnz; j++)
                g_csr[g_rowptr[erow[j]] + g_epos[j]] =
                    make_int2(ecol[j] << 8, __float_as_int(eval[j]));
        }
    } else {
        size_t i = (size_t)(b - scat_blocks) * blockDim.x + threadIdx.x;
        const size_t total = (size_t)NNODES * FDIM / 8;
        if (i < total) {
            const float4* s = reinterpret_cast<const float4*>(feat) + i * 2;
            float4 a = s[0], bb = s[1];
            __half2 h0 = __floats2half2_rn(a.x, a.y);
            __half2 h1 = __floats2half2_rn(a.z, a.w);
            __half2 h2 = __floats2half2_rn(bb.x, bb.y);
            __half2 h3 = __floats2half2_rn(bb.z, bb.w);
            uint4 st = make_uint4(*reinterpret_cast<uint32_t*>(&h0),
                                  *reinterpret_cast<uint32_t*>(&h1),
                                  *reinterpret_cast<uint32_t*>(&h2),
                                  *reinterpret_cast<uint32_t*>(&h3));
            reinterpret_cast<uint4*>(g_featH)[i] = st;
        }
    }
}

// ---------------------------------------------------------------------------
// SpMM-CSR, TWO rows per warp (16 lanes per row, uint4 = 8-half gathers).
// Edge fetch + gather + loop overhead amortize across 2 rows per warp-iter.
// fp32 accumulate; per-lane accumulation order identical to previous rounds.
// ---------------------------------------------------------------------------
__device__ __forceinline__ void unpack8(const uint4& h, float* f) {
    float2 a0 = __half22float2(*reinterpret_cast<const __half2*>(&h.x));
    float2 a1 = __half22float2(*reinterpret_cast<const __half2*>(&h.y));
    float2 a2 = __half22float2(*reinterpret_cast<const __half2*>(&h.z));
    float2 a3 = __half22float2(*reinterpret_cast<const __half2*>(&h.w));
    f[0] = a0.x; f[1] = a0.y; f[2] = a1.x; f[3] = a1.y;
    f[4] = a2.x; f[5] = a2.y; f[6] = a3.x; f[7] = a3.y;
}

__device__ __forceinline__ uint4 pack8(const float* f) {
    __half2 h0 = __floats2half2_rn(f[0], f[1]);
    __half2 h1 = __floats2half2_rn(f[2], f[3]);
    __half2 h2 = __floats2half2_rn(f[4], f[5]);
    __half2 h3 = __floats2half2_rn(f[6], f[7]);
    return make_uint4(*reinterpret_cast<uint32_t*>(&h0),
                      *reinterpret_cast<uint32_t*>(&h1),
                      *reinterpret_cast<uint32_t*>(&h2),
                      *reinterpret_cast<uint32_t*>(&h3));
}

__global__ __launch_bounds__(256)
void spmm1_csr_kernel() {
    int warp = threadIdx.x >> 5;
    int lane = threadIdx.x & 31;
    int sub  = lane & 15;                       // lane within row-group
    int row  = blockIdx.x * 16 + warp * 2 + (lane >> 4);
    if (row >= NNODES) return;

    const char* featB = reinterpret_cast<const char*>(g_featH) + sub * 16;
    int beg = g_rowptr[row];
    int end = g_rowptr[row + 1];

    float acc[8] = {0.f, 0.f, 0.f, 0.f, 0.f, 0.f, 0.f, 0.f};
    #pragma unroll 4
    for (int e = beg; e < end; e++) {
        int2  ed = g_csr[e];                    // broadcast within half-warp
        float v  = __int_as_float(ed.y);
        uint4 h = *reinterpret_cast<const uint4*>(featB + ed.x);
        float f[8];
        unpack8(h, f);
        #pragma unroll
        for (int q = 0; q < 8; q++) acc[q] = fmaf(v, f[q], acc[q]);
    }

    // own features
    uint4 hf = *reinterpret_cast<const uint4*>(featB + ((size_t)row << 8));
    float tf[8];
    unpack8(hf, tf);

    float lp[8], pp[8];
    #pragma unroll
    for (int q = 0; q < 8; q++) { lp[q] = acc[q] + tf[q]; pp[q] = acc[q] * tf[q]; }

    size_t off = ((size_t)row << 8) + sub * 16;
    *reinterpret_cast<uint4*>(reinterpret_cast<char*>(g_LfPH) + off) = pack8(lp);
    *reinterpret_cast<uint4*>(reinterpret_cast<char*>(g_PH)   + off) = pack8(pp);
}

__global__ __launch_bounds__(256)
void spmm2_csr_kernel() {
    int warp = threadIdx.x >> 5;
    int lane = threadIdx.x & 31;
    int sub  = lane & 15;
    int row  = blockIdx.x * 16 + warp * 2 + (lane >> 4);
    if (row >= NNODES) return;

    const char* pB = reinterpret_cast<const char*>(g_PH) + sub * 16;
    int beg = g_rowptr[row];
    int end = g_rowptr[row + 1];

    float acc[8] = {0.f, 0.f, 0.f, 0.f, 0.f, 0.f, 0.f, 0.f};
    #pragma unroll 4
    for (int e = beg; e < end; e++) {
        int2  ed = g_csr[e];
        float v  = __int_as_float(ed.y);
        uint4 h = *reinterpret_cast<const uint4*>(pB + ed.x);
        float f[8];
        unpack8(h, f);
        #pragma unroll
        for (int q = 0; q < 8; q++) acc[q] = fmaf(v, f[q], acc[q]);
    }

    size_t off = ((size_t)row << 8) + sub * 16;
    *reinterpret_cast<uint4*>(reinterpret_cast<char*>(g_LiH) + off) = pack8(acc);
}

// ---------------------------------------------------------------------------
// Persistent tensor-core GEMM (mma.sync m16n8k16 fp16, fp32 accum):
//   out = [LfPH ; LiH] (N x 256) @ [W1 ; W2] (256 x 128) + (b1+b2)
// ---------------------------------------------------------------------------
#define WTH 264
#define ASH 136
#define OFF_WT 0
#define OFF_AS (128 * WTH * 2)                       // 67584
#define OFF_BI (OFF_AS + 128 * ASH * 2)              // 102400
#define SMEM_GEMM (OFF_BI + 512)                     // 102912

static __device__ __forceinline__ void mma16(float* d,
                                             uint32_t a0, uint32_t a1,
                                             uint32_t a2, uint32_t a3,
                                             uint32_t b0, uint32_t b1) {
    asm volatile(
        "mma.sync.aligned.m16n8k16.row.col.f32.f16.f16.f32 "
        "{%0,%1,%2,%3}, {%4,%5,%6,%7}, {%8,%9}, {%0,%1,%2,%3};"
        : "+f"(d[0]), "+f"(d[1]), "+f"(d[2]), "+f"(d[3])
        : "r"(a0), "r"(a1), "r"(a2), "r"(a3), "r"(b0), "r"(b1));
}

__global__ __launch_bounds__(256)
void gemm_mma_kernel(const float* __restrict__ W1,
                     const float* __restrict__ b1,
                     const float* __restrict__ W2,
                     const float* __restrict__ b2,
                     float* __restrict__ out) {
    extern __shared__ char smem[];
    __half* Wt   = reinterpret_cast<__half*>(smem + OFF_WT);  // [128][264]
    __half* As   = reinterpret_cast<__half*>(smem + OFF_AS);  // [128][136]
    float*  bias = reinterpret_cast<float*>(smem + OFF_BI);

    const int tid  = threadIdx.x;
    const int w    = tid >> 5;
    const int lane = tid & 31;
    const int tg   = lane & 3;
    const int gid  = lane >> 2;
    const int wm   = w & 3;
    const int colg = w >> 2;

    #pragma unroll
    for (int it = 0; it < 32; it++) {
        int wt = it * 8 + w;
        int k0 = (wt >> 2) * 4;
        int n  = (wt & 3) * 32 + lane;
        const float* Wsrc = (k0 < 128) ? (W1 + (size_t)k0 * 128)
                                       : (W2 + (size_t)(k0 - 128) * 128);
        __half2 h01 = __floats2half2_rn(Wsrc[0 * 128 + n], Wsrc[1 * 128 + n]);
        __half2 h23 = __floats2half2_rn(Wsrc[2 * 128 + n], Wsrc[3 * 128 + n]);
        uint2 st = make_uint2(*reinterpret_cast<uint32_t*>(&h01),
                              *reinterpret_cast<uint32_t*>(&h23));
        *reinterpret_cast<uint2*>(Wt + n * WTH + k0) = st;
    }
    if (tid < 128) bias[tid] = b1[tid] + b2[tid];

    for (int tile = blockIdx.x; tile < NTILES; tile += gridDim.x) {
        const int row0 = tile * 128;

        float acc[2][8][4];
        #pragma unroll
        for (int s = 0; s < 2; s++)
            #pragma unroll
            for (int nt = 0; nt < 8; nt++)
                #pragma unroll
                for (int q = 0; q < 4; q++) acc[s][nt][q] = 0.f;

        #pragma unroll
        for (int phase = 0; phase < 2; phase++) {
            const __half* src = phase ? g_LiH : g_LfPH;
            __syncthreads();

            #pragma unroll
            for (int it = 0; it < 8; it++) {
                int idx = it * 256 + tid;
                int r = idx >> 4;
                int j = idx & 15;
                int row = row0 + r;
                if (row >= NNODES) row = NNODES - 1;
                uint4 v = reinterpret_cast<const uint4*>(
                              src + (size_t)row * FDIM)[j];
                *reinterpret_cast<uint4*>(As + r * ASH + j * 8) = v;
            }
            __syncthreads();

            const int kg0 = phase * 128;
            #pragma unroll 2
            for (int kb = 0; kb < 128; kb += 16) {
                uint32_t a[2][4];
                #pragma unroll
                for (int sub = 0; sub < 2; sub++) {
                    int rb = wm * 32 + sub * 16 + gid;
                    const __half* ap0 = As + rb * ASH + kb + 2 * tg;
                    const __half* ap1 = As + (rb + 8) * ASH + kb + 2 * tg;
                    a[sub][0] = *reinterpret_cast<const uint32_t*>(ap0);
                    a[sub][1] = *reinterpret_cast<const uint32_t*>(ap1);
                    a[sub][2] = *reinterpret_cast<const uint32_t*>(ap0 + 8);
                    a[sub][3] = *reinterpret_cast<const uint32_t*>(ap1 + 8);
                }
                #pragma unroll
                for (int nt = 0; nt < 8; nt++) {
                    int n = colg * 64 + nt * 8 + gid;
                    const __half* bp = Wt + n * WTH + kg0 + kb + 2 * tg;
                    uint32_t b0 = *reinterpret_cast<const uint32_t*>(bp);
                    uint32_t b1 = *reinterpret_cast<const uint32_t*>(bp + 8);
                    mma16(acc[0][nt], a[0][0], a[0][1], a[0][2], a[0][3], b0, b1);
                    mma16(acc[1][nt], a[1][0], a[1][1], a[1][2], a[1][3], b0, b1);
                }
            }
        }

        #pragma unroll
        for (int sub = 0; sub < 2; sub++) {
            int r0 = row0 + wm * 32 + sub * 16 + gid;
            #pragma unroll
            for (int nt = 0; nt < 8; nt++) {
                int c = colg * 64 + nt * 8 + tg * 2;
                float bx = bias[c], by = bias[c + 1];
                if (r0 < NNODES) {
                    float2 o = make_float2(acc[sub][nt][0] + bx, acc[sub][nt][1] + by);
                    *reinterpret_cast<float2*>(out + (size_t)r0 * FDIM + c) = o;
                }
                if (r0 + 8 < NNODES) {
                    float2 o = make_float2(acc[sub][nt][2] + bx, acc[sub][nt][3] + by);
                    *reinterpret_cast<float2*>(out + (size_t)(r0 + 8) * FDIM + c) = o;
                }
            }
        }
    }
}

// ---------------------------------------------------------------------------
extern "C" void kernel_launch(void* const* d_in, const int* in_sizes, int n_in,
                              void* d_out, int out_size) {
    const float* feat = (const float*)d_in[0];
    const float* eval = (const float*)d_in[1];
    const float* W1   = (const float*)d_in[2];
    const float* b1   = (const float*)d_in[3];
    const float* W2   = (const float*)d_in[4];
    const float* b2   = (const float*)d_in[5];
    const int*   erow = (const int*)d_in[6];
    const int*   ecol = (const int*)d_in[7];
    float*       out  = (float*)d_out;

    const int nnz = in_sizes[1];

    // zero row counts (graph memset node)
    {
        void* p = nullptr;
        cudaGetSymbolAddress(&p, g_rowcnt);
        cudaMemsetAsync(p, 0, NNODES * sizeof(int));
    }

    // hist (+ per-edge slot assignment) + scan-flag clear
    {
        int hist_blocks = (nnz / 4 + 255) / 256;
        hist_kernel<<<hist_blocks + 1, 256>>>(erow, nnz, hist_blocks);
    }

    // single-kernel decoupled-lookback scan
    scan_lookback_kernel<<<SCAN_G, SCAN_B>>>();

    // fused: atomic-free scatter || fp16 feature copy
    {
        int scat_blocks = (nnz / 4 + 255) / 256;
        int cvt_blocks  = (int)(((size_t)NNODES * FDIM / 8 + 255) / 256);
        fused_scatter_cvt_kernel<<<scat_blocks + cvt_blocks, 256>>>(
            eval, erow, ecol, feat, nnz, scat_blocks);
    }

    // SpMM passes (2 rows per warp, uint4 fp16 gathers)
    {
        int blocks = (NNODES + 15) / 16;
        spmm1_csr_kernel<<<blocks, 256>>>();
        spmm2_csr_kernel<<<blocks, 256>>>();
    }

    // GEMM (persistent, mma.sync fp16 m16n8k16, 2 CTAs/SM)
    {
        cudaFuncSetAttribute(gemm_mma_kernel,
                             cudaFuncAttributeMaxDynamicSharedMemorySize,
                             SMEM_GEMM);
        gemm_mma_kernel<<<296, 256, SMEM_GEMM>>>(W1, b1, W2, b2, out);
    }
}

// round 14
// speedup vs baseline: 1.1213x; 1.0099x over previous
#include <cuda_runtime.h>
#include <cuda_fp16.h>
#include <cstdint>

#define NNODES 100000
#define FDIM   128
#define NTILES ((NNODES + 127) / 128)

// ---- device-global scratch (allocations forbidden) ----
__device__ __half g_LfPH[(size_t)NNODES * FDIM]; // Lf + feat  fp16 (GEMM A, k 0..127)
__device__ __half g_LiH [(size_t)NNODES * FDIM]; // A @ P      fp16 (GEMM A, k 128..255)
__device__ __half g_featH[(size_t)NNODES * FDIM];// fp16 copy of features
__device__ __half g_PH  [(size_t)NNODES * FDIM]; // Lf * feat fp16 (spmm2 input)
__device__ int    g_rowcnt[NNODES];
__device__ int    g_rowptr[NNODES + 1];
__device__ int    g_epos[1600000 + 1024];        // per-edge slot within its row
__device__ int2   g_csr[1600000 + 1024];         // (col*256 byte-off, float_bits(val))

#define SCAN_B 1024
#define SCAN_G ((NNODES + SCAN_B - 1) / SCAN_B)  // 98
__device__ unsigned long long g_scanpkt[SCAN_G];

// ---------------------------------------------------------------------------
// hist: count edges per row AND record each edge's slot within its row.
// Last block clears scan flags.
// ---------------------------------------------------------------------------
__global__ void hist_kernel(const int* __restrict__ erow, int nnz,
                            int hist_blocks) {
    int b = blockIdx.x;
    if (b < hist_blocks) {
        int i = (b * blockDim.x + threadIdx.x) * 4;
        if (i + 3 < nnz) {
            int4 r = *reinterpret_cast<const int4*>(erow + i);
            int4 p;
            p.x = atomicAdd(&g_rowcnt[r.x], 1);
            p.y = atomicAdd(&g_rowcnt[r.y], 1);
            p.z = atomicAdd(&g_rowcnt[r.z], 1);
            p.w = atomicAdd(&g_rowcnt[r.w], 1);
            *reinterpret_cast<int4*>(g_epos + i) = p;
        } else {
            for (int j = i; j < nnz; j++)
                g_epos[j] = atomicAdd(&g_rowcnt[erow[j]], 1);
        }
    } else {
        if (threadIdx.x < SCAN_G) g_scanpkt[threadIdx.x] = 0ull;
    }
}

// ---------------------------------------------------------------------------
// Single-kernel exclusive scan (decoupled lookback, 98 co-resident blocks).
// ---------------------------------------------------------------------------
__global__ __launch_bounds__(SCAN_B, 1)
void scan_lookback_kernel() {
    __shared__ int s[SCAN_B];
    __shared__ int s_excl;
    const int tid = threadIdx.x;
    const int b   = blockIdx.x;
    const int i   = b * SCAN_B + tid;
    int v = (i < NNODES) ? g_rowcnt[i] : 0;

    s[tid] = v;
    __syncthreads();
    for (int off = 1; off < SCAN_B; off <<= 1) {
        int t = (tid >= off) ? s[tid - off] : 0;
        __syncthreads();
        s[tid] += t;
        __syncthreads();
    }
    int incl  = s[tid];
    int total = s[SCAN_B - 1];

    if (tid == 0) {
        volatile unsigned long long* pkt = g_scanpkt;
        if (b == 0) {
            pkt[0] = ((unsigned long long)2 << 32) | (unsigned int)total;
            s_excl = 0;
        } else {
            pkt[b] = ((unsigned long long)1 << 32) | (unsigned int)total;
            int excl = 0;
            for (int j = b - 1; j >= 0; ) {
                unsigned long long p;
                do { p = pkt[j]; } while ((p >> 32) == 0ull);
                excl += (int)(unsigned int)p;
                if ((p >> 32) == 2ull) break;
                j--;
            }
            pkt[b] = ((unsigned long long)2 << 32) | (unsigned int)(excl + total);
            s_excl = excl;
        }
    }
    __syncthreads();

    int excl = s_excl + incl - v;
    if (i < NNODES) {
        g_rowptr[i] = excl;
        if (i == NNODES - 1) g_rowptr[NNODES] = excl + v;
    }
}

// ---------------------------------------------------------------------------
// Fused: [scat blocks] atomic-free CSR scatter | [cvt blocks] feat->fp16 copy
// ---------------------------------------------------------------------------
__global__ void fused_scatter_cvt_kernel(const float* __restrict__ eval,
                                         const int*   __restrict__ erow,
                                         const int*   __restrict__ ecol,
                                         const float* __restrict__ feat,
                                         int nnz, int scat_blocks) {
    int b = blockIdx.x;
    if (b < scat_blocks) {
        int i = (b * blockDim.x + threadIdx.x) * 4;
        if (i + 3 < nnz) {
            int4   r = *reinterpret_cast<const int4*>(erow + i);
            int4   c = *reinterpret_cast<const int4*>(ecol + i);
            int4   p = *reinterpret_cast<const int4*>(g_epos + i);
            float4 v = *reinterpret_cast<const float4*>(eval + i);
            g_csr[g_rowptr[r.x] + p.x] = make_int2(c.x << 8, __float_as_int(v.x));
            g_csr[g_rowptr[r.y] + p.y] = make_int2(c.y << 8, __float_as_int(v.y));
            g_csr[g_rowptr[r.z] + p.z] = make_int2(c.z << 8, __float_as_int(v.z));
            g_csr[g_rowptr[r.w] + p.w] = make_int2(c.w << 8, __float_as_int(v.w));
        } else {
            for (int j = i; j < nnz; j++)
                g_csr[g_rowptr[erow[j]] + g_epos[j]] =
                    make_int2(ecol[j] << 8, __float_as_int(eval[j]));
        }
    } else {
        size_t i = (size_t)(b - scat_blocks) * blockDim.x + threadIdx.x;
        const size_t total = (size_t)NNODES * FDIM / 8;
        if (i < total) {
            const float4* s = reinterpret_cast<const float4*>(feat) + i * 2;
            float4 a = s[0], bb = s[1];
            __half2 h0 = __floats2half2_rn(a.x, a.y);
            __half2 h1 = __floats2half2_rn(a.z, a.w);
            __half2 h2 = __floats2half2_rn(bb.x, bb.y);
            __half2 h3 = __floats2half2_rn(bb.z, bb.w);
            uint4 st = make_uint4(*reinterpret_cast<uint32_t*>(&h0),
                                  *reinterpret_cast<uint32_t*>(&h1),
                                  *reinterpret_cast<uint32_t*>(&h2),
                                  *reinterpret_cast<uint32_t*>(&h3));
            reinterpret_cast<uint4*>(g_featH)[i] = st;
        }
    }
}

// ---------------------------------------------------------------------------
// SpMM-CSR, 2 rows/warp (16 lanes/row, uint4 gathers), paired edge fetch.
// fp32 accumulate; per-lane accumulation order unchanged (bit-identical).
// ---------------------------------------------------------------------------
__device__ __forceinline__ void unpack8(const uint4& h, float* f) {
    float2 a0 = __half22float2(*reinterpret_cast<const __half2*>(&h.x));
    float2 a1 = __half22float2(*reinterpret_cast<const __half2*>(&h.y));
    float2 a2 = __half22float2(*reinterpret_cast<const __half2*>(&h.z));
    float2 a3 = __half22float2(*reinterpret_cast<const __half2*>(&h.w));
    f[0] = a0.x; f[1] = a0.y; f[2] = a1.x; f[3] = a1.y;
    f[4] = a2.x; f[5] = a2.y; f[6] = a3.x; f[7] = a3.y;
}

__device__ __forceinline__ uint4 pack8(const float* f) {
    __half2 h0 = __floats2half2_rn(f[0], f[1]);
    __half2 h1 = __floats2half2_rn(f[2], f[3]);
    __half2 h2 = __floats2half2_rn(f[4], f[5]);
    __half2 h3 = __floats2half2_rn(f[6], f[7]);
    return make_uint4(*reinterpret_cast<uint32_t*>(&h0),
                      *reinterpret_cast<uint32_t*>(&h1),
                      *reinterpret_cast<uint32_t*>(&h2),
                      *reinterpret_cast<uint32_t*>(&h3));
}

__device__ __forceinline__ void gather_row_fma(const char* baseB, int off,
                                               float v, float* acc) {
    uint4 h = *reinterpret_cast<const uint4*>(baseB + off);
    float f[8];
    unpack8(h, f);
    #pragma unroll
    for (int q = 0; q < 8; q++) acc[q] = fmaf(v, f[q], acc[q]);
}

__device__ __forceinline__ void spmm_row_accum(const char* baseB,
                                               int beg, int end, float* acc) {
    int e = beg;
    if (e < end && (e & 1)) {                   // peel to 16B alignment
        int2 ed = g_csr[e];
        gather_row_fma(baseB, ed.x, __int_as_float(ed.y), acc);
        e++;
    }
    #pragma unroll 2
    for (; e + 1 < end; e += 2) {               // paired LDG.128 edge fetch
        int4 ep = *reinterpret_cast<const int4*>(g_csr + e);
        gather_row_fma(baseB, ep.x, __int_as_float(ep.y), acc);
        gather_row_fma(baseB, ep.z, __int_as_float(ep.w), acc);
    }
    if (e < end) {
        int2 ed = g_csr[e];
        gather_row_fma(baseB, ed.x, __int_as_float(ed.y), acc);
    }
}

__global__ __launch_bounds__(256)
void spmm1_csr_kernel() {
    int warp = threadIdx.x >> 5;
    int lane = threadIdx.x & 31;
    int sub  = lane & 15;
    int row  = blockIdx.x * 16 + warp * 2 + (lane >> 4);
    if (row >= NNODES) return;

    const char* featB = reinterpret_cast<const char*>(g_featH) + sub * 16;
    int beg = g_rowptr[row];
    int end = g_rowptr[row + 1];

    float acc[8] = {0.f, 0.f, 0.f, 0.f, 0.f, 0.f, 0.f, 0.f};
    spmm_row_accum(featB, beg, end, acc);

    uint4 hf = *reinterpret_cast<const uint4*>(featB + ((size_t)row << 8));
    float tf[8];
    unpack8(hf, tf);

    float lp[8], pp[8];
    #pragma unroll
    for (int q = 0; q < 8; q++) { lp[q] = acc[q] + tf[q]; pp[q] = acc[q] * tf[q]; }

    size_t off = ((size_t)row << 8) + sub * 16;
    *reinterpret_cast<uint4*>(reinterpret_cast<char*>(g_LfPH) + off) = pack8(lp);
    *reinterpret_cast<uint4*>(reinterpret_cast<char*>(g_PH)   + off) = pack8(pp);
}

__global__ __launch_bounds__(256)
void spmm2_csr_kernel() {
    int warp = threadIdx.x >> 5;
    int lane = threadIdx.x & 31;
    int sub  = lane & 15;
    int row  = blockIdx.x * 16 + warp * 2 + (lane >> 4);
    if (row >= NNODES) return;

    const char* pB = reinterpret_cast<const char*>(g_PH) + sub * 16;
    int beg = g_rowptr[row];
    int end = g_rowptr[row + 1];

    float acc[8] = {0.f, 0.f, 0.f, 0.f, 0.f, 0.f, 0.f, 0.f};
    spmm_row_accum(pB, beg, end, acc);

    size_t off = ((size_t)row << 8) + sub * 16;
    *reinterpret_cast<uint4*>(reinterpret_cast<char*>(g_LiH) + off) = pack8(acc);
}

// ---------------------------------------------------------------------------
// Persistent tensor-core GEMM (mma.sync m16n8k16 fp16, fp32 accum):
//   out = [LfPH ; LiH] (N x 256) @ [W1 ; W2] (256 x 128) + (b1+b2)
// Per-warp-pair named barriers: warps {wm, wm+4} privately own As rows
// [wm*32, wm*32+32) -> no block-wide sync in the tile loop.
// ---------------------------------------------------------------------------
#define WTH 264
#define ASH 136
#define OFF_WT 0
#define OFF_AS (128 * WTH * 2)                       // 67584
#define OFF_BI (OFF_AS + 128 * ASH * 2)              // 102400
#define SMEM_GEMM (OFF_BI + 512)                     // 102912

static __device__ __forceinline__ void mma16(float* d,
                                             uint32_t a0, uint32_t a1,
                                             uint32_t a2, uint32_t a3,
                                             uint32_t b0, uint32_t b1) {
    asm volatile(
        "mma.sync.aligned.m16n8k16.row.col.f32.f16.f16.f32 "
        "{%0,%1,%2,%3}, {%4,%5,%6,%7}, {%8,%9}, {%0,%1,%2,%3};"
        : "+f"(d[0]), "+f"(d[1]), "+f"(d[2]), "+f"(d[3])
        : "r"(a0), "r"(a1), "r"(a2), "r"(a3), "r"(b0), "r"(b1));
}

__global__ __launch_bounds__(256)
void gemm_mma_kernel(const float* __restrict__ W1,
                     const float* __restrict__ b1,
                     const float* __restrict__ W2,
                     const float* __restrict__ b2,
                     float* __restrict__ out) {
    extern __shared__ char smem[];
    __half* Wt   = reinterpret_cast<__half*>(smem + OFF_WT);  // [128][264]
    __half* As   = reinterpret_cast<__half*>(smem + OFF_AS);  // [128][136]
    float*  bias = reinterpret_cast<float*>(smem + OFF_BI);

    const int tid  = threadIdx.x;
    const int w    = tid >> 5;
    const int lane = tid & 31;
    const int tg   = lane & 3;
    const int gid  = lane >> 2;
    const int wm   = w & 3;
    const int colg = w >> 2;
    const int bar  = 1 + wm;      // named barrier id for the {wm, wm+4} pair

    #pragma unroll
    for (int it = 0; it < 32; it++) {
        int wt = it * 8 + w;
        int k0 = (wt >> 2) * 4;
        int n  = (wt & 3) * 32 + lane;
        const float* Wsrc = (k0 < 128) ? (W1 + (size_t)k0 * 128)
                                       : (W2 + (size_t)(k0 - 128) * 128);
        __half2 h01 = __floats2half2_rn(Wsrc[0 * 128 + n], Wsrc[1 * 128 + n]);
        __half2 h23 = __floats2half2_rn(Wsrc[2 * 128 + n], Wsrc[3 * 128 + n]);
        uint2 st = make_uint2(*reinterpret_cast<uint32_t*>(&h01),
                              *reinterpret_cast<uint32_t*>(&h23));
        *reinterpret_cast<uint2*>(Wt + n * WTH + k0) = st;
    }
    if (tid < 128) bias[tid] = b1[tid] + b2[tid];
    __syncthreads();   // Wt + bias ready (read-only afterwards)

    for (int tile = blockIdx.x; tile < NTILES; tile += gridDim.x) {
        const int row0 = tile * 128;

        float acc[2][8][4];
        #pragma unroll
        for (int s = 0; s < 2; s++)
            #pragma unroll
            for (int nt = 0; nt < 8; nt++)
                #pragma unroll
                for (int q = 0; q < 4; q++) acc[s][nt][q] = 0.f;

        #pragma unroll
        for (int phase = 0; phase < 2; phase++) {
            const __half* src = phase ? g_LiH : g_LfPH;

            // pair barrier: partner done reading As region from prior phase/tile
            asm volatile("bar.sync %0, 64;" :: "r"(bar) : "memory");

            // this warp stages its own 16 rows: wm*32 + colg*16 + 0..15
            #pragma unroll
            for (int it = 0; it < 8; it++) {
                int idx = it * 32 + lane;           // 0..255
                int r = wm * 32 + colg * 16 + (idx >> 4);
                int j = idx & 15;
                int row = row0 + r;
                if (row >= NNODES) row = NNODES - 1;
                uint4 v = reinterpret_cast<const uint4*>(
                              src + (size_t)row * FDIM)[j];
                *reinterpret_cast<uint4*>(As + r * ASH + j * 8) = v;
            }
            asm volatile("bar.sync %0, 64;" :: "r"(bar) : "memory");

            const int kg0 = phase * 128;
            #pragma unroll 2
            for (int kb = 0; kb < 128; kb += 16) {
                uint32_t a[2][4];
                #pragma unroll
                for (int sub = 0; sub < 2; sub++) {
                    int rb = wm * 32 + sub * 16 + gid;
                    const __half* ap0 = As + rb * ASH + kb + 2 * tg;
                    const __half* ap1 = As + (rb + 8) * ASH + kb + 2 * tg;
                    a[sub][0] = *reinterpret_cast<const uint32_t*>(ap0);
                    a[sub][1] = *reinterpret_cast<const uint32_t*>(ap1);
                    a[sub][2] = *reinterpret_cast<const uint32_t*>(ap0 + 8);
                    a[sub][3] = *reinterpret_cast<const uint32_t*>(ap1 + 8);
                }
                #pragma unroll
                for (int nt = 0; nt < 8; nt++) {
                    int n = colg * 64 + nt * 8 + gid;
                    const __half* bp = Wt + n * WTH + kg0 + kb + 2 * tg;
                    uint32_t b0 = *reinterpret_cast<const uint32_t*>(bp);
                    uint32_t b1 = *reinterpret_cast<const uint32_t*>(bp + 8);
                    mma16(acc[0][nt], a[0][0], a[0][1], a[0][2], a[0][3], b0, b1);
                    mma16(acc[1][nt], a[1][0], a[1][1], a[1][2], a[1][3], b0, b1);
                }
            }
        }

        #pragma unroll
        for (int sub = 0; sub < 2; sub++) {
            int r0 = row0 + wm * 32 + sub * 16 + gid;
            #pragma unroll
            for (int nt = 0; nt < 8; nt++) {
                int c = colg * 64 + nt * 8 + tg * 2;
                float bx = bias[c], by = bias[c + 1];
                if (r0 < NNODES) {
                    float2 o = make_float2(acc[sub][nt][0] + bx, acc[sub][nt][1] + by);
                    *reinterpret_cast<float2*>(out + (size_t)r0 * FDIM + c) = o;
                }
                if (r0 + 8 < NNODES) {
                    float2 o = make_float2(acc[sub][nt][2] + bx, acc[sub][nt][3] + by);
                    *reinterpret_cast<float2*>(out + (size_t)(r0 + 8) * FDIM + c) = o;
                }
            }
        }
    }
}

// ---------------------------------------------------------------------------
extern "C" void kernel_launch(void* const* d_in, const int* in_sizes, int n_in,
                              void* d_out, int out_size) {
    const float* feat = (const float*)d_in[0];
    const float* eval = (const float*)d_in[1];
    const float* W1   = (const float*)d_in[2];
    const float* b1   = (const float*)d_in[3];
    const float* W2   = (const float*)d_in[4];
    const float* b2   = (const float*)d_in[5];
    const int*   erow = (const int*)d_in[6];
    const int*   ecol = (const int*)d_in[7];
    float*       out  = (float*)d_out;

    const int nnz = in_sizes[1];

    // zero row counts (graph memset node)
    {
        void* p = nullptr;
        cudaGetSymbolAddress(&p, g_rowcnt);
        cudaMemsetAsync(p, 0, NNODES * sizeof(int));
    }

    // hist (+ per-edge slot assignment) + scan-flag clear
    {
        int hist_blocks = (nnz / 4 + 255) / 256;
        hist_kernel<<<hist_blocks + 1, 256>>>(erow, nnz, hist_blocks);
    }

    // single-kernel decoupled-lookback scan
    scan_lookback_kernel<<<SCAN_G, SCAN_B>>>();

    // fused: atomic-free scatter || fp16 feature copy
    {
        int scat_blocks = (nnz / 4 + 255) / 256;
        int cvt_blocks  = (int)(((size_t)NNODES * FDIM / 8 + 255) / 256);
        fused_scatter_cvt_kernel<<<scat_blocks + cvt_blocks, 256>>>(
            eval, erow, ecol, feat, nnz, scat_blocks);
    }

    // SpMM passes (2 rows per warp, paired edge fetch, uint4 fp16 gathers)
    {
        int blocks = (NNODES + 15) / 16;
        spmm1_csr_kernel<<<blocks, 256>>>();
        spmm2_csr_kernel<<<blocks, 256>>>();
    }

    // GEMM (persistent, mma.sync fp16 m16n8k16, pair-barrier pipeline)
    {
        cudaFuncSetAttribute(gemm_mma_kernel,
                             cudaFuncAttributeMaxDynamicSharedMemorySize,
                             SMEM_GEMM);
        gemm_mma_kernel<<<296, 256, SMEM_GEMM>>>(W1, b1, W2, b2, out);
    }
}